// round 9
// baseline (speedup 1.0000x reference)
#include <cuda_runtime.h>
#include <math.h>

#define N_NODES 200000
#define N_EDGES 1000000
#define HDIM    64
#define NGRAPH  512
#define NCLS    10
#define BN_EPS  1e-5f

#define SCAN_CHUNK 1024
#define SCAN_BLKS  ((N_NODES + SCAN_CHUNK - 1) / SCAN_CHUNK)   // 196
#define NBUCKET 64
#define PSUM_STRIDE (NBUCKET * 2 * HDIM)            // 8192 doubles per layer
#define ADJ_TOTAL (N_EDGES + 3 * N_NODES)           // padded adjacency capacity

// ---------------- static device scratch ----------------
__device__ __align__(256) float  g_buf1[(size_t)(N_NODES + 1) * HDIM]; // h (row N = zeros)
__device__ __align__(256) float  g_buf2[(size_t)N_NODES * HDIM];       // AGG layer 1
__device__ __align__(256) float  g_buf3[(size_t)N_NODES * HDIM];       // AGG layer 2
__device__ __align__(256) int    g_adj[ADJ_TOTAL];
__device__ __align__(256) int    g_cnt[N_NODES];
__device__ __align__(256) int2   g_row2[N_NODES];                      // {rowstart, cnt_padded}
__device__ __align__(256) int    g_cursor[N_NODES];
__device__ __align__(256) int    g_localex[N_NODES];
__device__ __align__(16)  int    g_blksum[256];
__device__ __align__(256) float  g_dinv[N_NODES + 1];                  // [N] = 0 for dummies
__device__ __align__(256) double g_psums[2 * PSUM_STRIDE];
__device__ __align__(16)  float  g_scale[HDIM];
__device__ __align__(16)  float  g_shift[HDIM];
__device__ __align__(256) float  g_pool1[NGRAPH * HDIM];               // relu1 partial sums
__device__ int g_done;

// ---------------- init: fill adj with dummy idx, zero everything ----------------
__global__ void init_kernel(int* __restrict__ adj, int* __restrict__ cnt,
                            double* __restrict__ psums, float* __restrict__ pool1,
                            float* __restrict__ buf1, float* __restrict__ dinv,
                            int* __restrict__ done) {
    int i = blockIdx.x * blockDim.x + threadIdx.x;
    if (i < ADJ_TOTAL) adj[i] = N_NODES;            // dummy -> zero row
    if (i < N_NODES) cnt[i] = 0;
    if (i < 2 * PSUM_STRIDE) psums[i] = 0.0;
    if (i < NGRAPH * HDIM) pool1[i] = 0.0f;
    if (i < HDIM) buf1[(size_t)N_NODES * HDIM + i] = 0.0f;
    if (i == 0) { *done = 0; dinv[N_NODES] = 0.0f; }
}

__global__ void deg_count_kernel(const int* __restrict__ dst, int* __restrict__ cnt) {
    int i = blockIdx.x * blockDim.x + threadIdx.x;
    if (i >= N_EDGES / 4) return;
    int4 d = __ldg((const int4*)dst + i);
    atomicAdd(&cnt[d.x], 1);
    atomicAdd(&cnt[d.y], 1);
    atomicAdd(&cnt[d.z], 1);
    atomicAdd(&cnt[d.w], 1);
}

// ---------------- scan over PADDED counts ----------------
__global__ void scanA_kernel(const int* __restrict__ cnt, int* __restrict__ localex,
                             int* __restrict__ blksum) {
    __shared__ int sh[256];
    int b = blockIdx.x, t = threadIdx.x;
    int base = b * SCAN_CHUNK + t * 4;
    int v0 = (base + 0 < N_NODES) ? ((cnt[base + 0] + 3) & ~3) : 0;
    int v1 = (base + 1 < N_NODES) ? ((cnt[base + 1] + 3) & ~3) : 0;
    int v2 = (base + 2 < N_NODES) ? ((cnt[base + 2] + 3) & ~3) : 0;
    int v3 = (base + 3 < N_NODES) ? ((cnt[base + 3] + 3) & ~3) : 0;
    int s = v0 + v1 + v2 + v3;
    sh[t] = s;
    __syncthreads();
#pragma unroll
    for (int off = 1; off < 256; off <<= 1) {
        int x = (t >= off) ? sh[t - off] : 0;
        __syncthreads();
        sh[t] += x;
        __syncthreads();
    }
    int excl = sh[t] - s;
    if (t == 255) blksum[b] = sh[255];
    if (base + 0 < N_NODES) localex[base + 0] = excl;  excl += v0;
    if (base + 1 < N_NODES) localex[base + 1] = excl;  excl += v1;
    if (base + 2 < N_NODES) localex[base + 2] = excl;  excl += v2;
    if (base + 3 < N_NODES) localex[base + 3] = excl;
}

__global__ void scanC_kernel(const int* __restrict__ localex, const int* __restrict__ blksum,
                             const int* __restrict__ cnt,
                             int2* __restrict__ row2, int* __restrict__ cursor,
                             float* __restrict__ dinv) {
    __shared__ int sh[256];
    __shared__ int pre[256];
    int t = threadIdx.x;
    int v = (t < SCAN_BLKS) ? blksum[t] : 0;
    sh[t] = v;
    __syncthreads();
#pragma unroll
    for (int off = 1; off < 256; off <<= 1) {
        int x = (t >= off) ? sh[t - off] : 0;
        __syncthreads();
        sh[t] += x;
        __syncthreads();
    }
    pre[t] = sh[t] - v;
    __syncthreads();

    int i = blockIdx.x * 256 + t;
    if (i < N_NODES) {
        int c = cnt[i];
        int r = localex[i] + pre[i >> 10];
        row2[i] = make_int2(r, (c + 3) & ~3);       // padded count
        cursor[i] = r;
        dinv[i] = rsqrtf((float)(c + 1));
    }
}

__global__ void scatter_kernel(const int* __restrict__ src, const int* __restrict__ dst,
                               int* __restrict__ cursor, int* __restrict__ adj) {
    int i = blockIdx.x * blockDim.x + threadIdx.x;
    if (i >= N_EDGES / 4) return;
    int4 s = __ldg((const int4*)src + i);
    int4 d = __ldg((const int4*)dst + i);
    adj[atomicAdd(&cursor[d.x], 1)] = s.x;
    adj[atomicAdd(&cursor[d.y], 1)] = s.y;
    adj[atomicAdd(&cursor[d.z], 1)] = s.z;
    adj[atomicAdd(&cursor[d.w], 1)] = s.w;
}

// ---------------- 64x64 GEMM, 4x4 register tiles ----------------
// FUSED: applies relu(BN1(.)) to the input on load, and accumulates per-graph
// partial sums of that relu1 input into pool1 (residual pooling).
template <bool FUSED>
__global__ void __launch_bounds__(256) gemm64_kernel(
        const float* __restrict__ X, const float* __restrict__ W,
        const float* __restrict__ scale, const float* __restrict__ shift,
        const int* __restrict__ batch, float* __restrict__ pool1,
        float* __restrict__ HP) {
    __shared__ __align__(16) float Ws[64 * 64];   // [k][col]
    __shared__ __align__(16) float Xt[64 * 68];   // [k][row]
    __shared__ int sbatch[64];

    int tid  = threadIdx.x;
    int row0 = blockIdx.x * 64;

    float sc = 1.0f, sh = 0.0f;
    if (FUSED) {
        sc = __ldg(scale + (tid & 63));
        sh = __ldg(shift + (tid & 63));
        if (tid < 64) sbatch[tid] = batch[row0 + tid];
    }

#pragma unroll
    for (int j = 0; j < 16; j++) Ws[tid + j * 256] = W[tid + j * 256];
#pragma unroll
    for (int j = 0; j < 16; j++) {
        int idx = tid + j * 256;
        float v = X[(size_t)row0 * 64 + idx];
        if (FUSED) v = fmaxf(fmaf(v, sc, sh), 0.0f);
        Xt[(idx & 63) * 68 + (idx >> 6)] = v;
    }
    __syncthreads();

    int tr = tid >> 4, tc = tid & 15;
    float acc[4][4];
#pragma unroll
    for (int i = 0; i < 4; i++)
#pragma unroll
        for (int j = 0; j < 4; j++) acc[i][j] = 0.0f;

#pragma unroll
    for (int k = 0; k < 64; k++) {
        float4 xv = *(const float4*)&Xt[k * 68 + 4 * tr];
        float4 wv = *(const float4*)&Ws[k * 64 + 4 * tc];
        acc[0][0] += xv.x * wv.x; acc[0][1] += xv.x * wv.y; acc[0][2] += xv.x * wv.z; acc[0][3] += xv.x * wv.w;
        acc[1][0] += xv.y * wv.x; acc[1][1] += xv.y * wv.y; acc[1][2] += xv.y * wv.z; acc[1][3] += xv.y * wv.w;
        acc[2][0] += xv.z * wv.x; acc[2][1] += xv.z * wv.y; acc[2][2] += xv.z * wv.z; acc[2][3] += xv.z * wv.w;
        acc[3][0] += xv.w * wv.x; acc[3][1] += xv.w * wv.y; acc[3][2] += xv.w * wv.z; acc[3][3] += xv.w * wv.w;
    }

#pragma unroll
    for (int i = 0; i < 4; i++) {
        float4 o;
        o.x = acc[i][0]; o.y = acc[i][1]; o.z = acc[i][2]; o.w = acc[i][3];
        *(float4*)&HP[(size_t)(row0 + 4 * tr + i) * 64 + 4 * tc] = o;
    }

    if (FUSED && tid < 64) {   // residual pooling of relu1 rows (batch-sorted)
        int f = tid;
        float s = 0.0f;
        int curg = sbatch[0];
        for (int r = 0; r < 64; r++) {
            int gg = sbatch[r];
            if (gg != curg) { atomicAdd(&pool1[curg * 64 + f], s); s = 0.0f; curg = gg; }
            s += Xt[f * 68 + r];
        }
        atomicAdd(&pool1[curg * 64 + f], s);
    }
}

// ---------------- CSR gather aggregation + fused BN stats (+optional finalize) --------
template <bool FINALIZE>
__global__ void __launch_bounds__(256) agg_kernel(
        const int2* __restrict__ row2, const int* __restrict__ adj,
        const float* __restrict__ dinv,
        const float* __restrict__ HP, float* __restrict__ AGG,
        double* __restrict__ psums, int* __restrict__ done,
        const float* __restrict__ gw, const float* __restrict__ be,
        float* __restrict__ scale, float* __restrict__ shift) {
    int tid  = threadIdx.x;
    int node = blockIdx.x * 16 + (tid >> 4);
    int part = tid & 15;
    const float4* Hp = (const float4*)HP;

    float dd = __ldg(dinv + node);
    float4 self = __ldg(Hp + (size_t)node * 16 + part);
    float4 acc;
    acc.x = self.x * dd; acc.y = self.y * dd;
    acc.z = self.z * dd; acc.w = self.w * dd;

    int2 rc = __ldg(row2 + node);
    int beg = rc.x, cpad = rc.y;
    for (int j = 0; j < cpad; j += 4) {            // fully padded: no tail
        int s0 = __ldg(adj + beg + j);
        int s1 = __ldg(adj + beg + j + 1);
        int s2 = __ldg(adj + beg + j + 2);
        int s3 = __ldg(adj + beg + j + 3);
        float d0 = __ldg(dinv + s0);
        float d1 = __ldg(dinv + s1);
        float d2 = __ldg(dinv + s2);
        float d3 = __ldg(dinv + s3);
        float4 a = __ldg(Hp + (size_t)s0 * 16 + part);
        float4 b = __ldg(Hp + (size_t)s1 * 16 + part);
        float4 c = __ldg(Hp + (size_t)s2 * 16 + part);
        float4 e = __ldg(Hp + (size_t)s3 * 16 + part);
        acc.x = fmaf(a.x, d0, fmaf(b.x, d1, fmaf(c.x, d2, fmaf(e.x, d3, acc.x))));
        acc.y = fmaf(a.y, d0, fmaf(b.y, d1, fmaf(c.y, d2, fmaf(e.y, d3, acc.y))));
        acc.z = fmaf(a.z, d0, fmaf(b.z, d1, fmaf(c.z, d2, fmaf(e.z, d3, acc.z))));
        acc.w = fmaf(a.w, d0, fmaf(b.w, d1, fmaf(c.w, d2, fmaf(e.w, d3, acc.w))));
    }
    acc.x *= dd; acc.y *= dd; acc.z *= dd; acc.w *= dd;
    ((float4*)AGG)[(size_t)node * 16 + part] = acc;

    // fused BN stats
    __shared__ float4 s_acc[256];
    s_acc[tid] = acc;
    __syncthreads();
    if (tid < HDIM) {
        const float* sa = (const float*)s_acc;
        float s = 0.0f, sq = 0.0f;
#pragma unroll
        for (int n = 0; n < 16; n++) {
            float v = sa[n * 64 + tid];
            s += v;
            sq += v * v;
        }
        int bucket = blockIdx.x & (NBUCKET - 1);
        atomicAdd(&psums[bucket * 128 + tid], (double)s);
        atomicAdd(&psums[bucket * 128 + HDIM + tid], (double)sq);
    }

    if (FINALIZE) {   // last block computes scale/shift (removes a launch)
        __shared__ int islast;
        __threadfence();
        __syncthreads();
        if (tid == 0) islast = (atomicAdd(done, 1) == (int)gridDim.x - 1);
        __syncthreads();
        if (islast && tid < HDIM) {
            __threadfence();
            int f = tid;
            double s = 0.0, sq = 0.0;
#pragma unroll 4
            for (int b = 0; b < NBUCKET; b++) {
                s  += psums[b * 128 + f];
                sq += psums[b * 128 + HDIM + f];
            }
            double mean = s / (double)N_NODES;
            double var  = sq / (double)N_NODES - mean * mean;
            float rs = rsqrtf((float)var + BN_EPS);
            float scv = rs * gw[f];
            scale[f] = scv;
            shift[f] = (float)(-mean) * scv + be[f];
        }
    }
}

// ---------------- fused: BN2-finalize + BN2 apply + pool2 + residual pool1 + head -----
__global__ void __launch_bounds__(512) poolhead_kernel(
        const float* __restrict__ AGG2, const float* __restrict__ pool1,
        const double* __restrict__ psums2,
        const float* __restrict__ g2, const float* __restrict__ be2,
        const int* __restrict__ batch,
        const float* __restrict__ lw1, const float* __restrict__ lb1,
        const float* __restrict__ lw2, const float* __restrict__ lb2,
        float* __restrict__ out) {
    int g = blockIdx.x;
    int tid = threadIdx.x;

    __shared__ float sc2s[64], sh2s[64];
    __shared__ int s_start, s_end;

    if (tid >= 64 && tid < 128) {
        int f = tid - 64;
        double s = 0.0, sq = 0.0;
#pragma unroll 4
        for (int b = 0; b < NBUCKET; b++) {
            s  += psums2[b * 128 + f];
            sq += psums2[b * 128 + HDIM + f];
        }
        double mean = s / (double)N_NODES;
        double var  = sq / (double)N_NODES - mean * mean;
        float rs = rsqrtf((float)var + BN_EPS);
        float sc = rs * g2[f];
        sc2s[f] = sc;
        sh2s[f] = (float)(-mean) * sc + be2[f];
    }
    if (tid == 0) {
        int lo = 0, hi = N_NODES;
        while (lo < hi) { int mid = (lo + hi) >> 1; if (batch[mid] < g) lo = mid + 1; else hi = mid; }
        s_start = lo;
        hi = N_NODES;
        while (lo < hi) { int mid = (lo + hi) >> 1; if (batch[mid] < g + 1) lo = mid + 1; else hi = mid; }
        s_end = lo;
    }
    __syncthreads();

    int start = s_start, end = s_end;
    int f = tid & 63;
    int grp = tid >> 6;
    float sc2 = sc2s[f], sh2 = sh2s[f];
    float s = 0.0f;
#pragma unroll 2
    for (int r = start + grp; r < end; r += 8) {
        float a2 = AGG2[(size_t)r * 64 + f];
        s += fmaxf(fmaf(a2, sc2, sh2), 0.0f);
    }
    __shared__ float shm[512];
    shm[tid] = s;
    __syncthreads();

    __shared__ float p[64];
    if (grp == 0) {
        float t = 0.0f;
#pragma unroll
        for (int q = 0; q < 8; q++) t += shm[f + q * 64];
        t += __ldg(pool1 + g * 64 + f);             // residual relu1 partial sum
        int cnt = end - start;
        p[f] = t / (float)(cnt > 0 ? cnt : 1);
    }
    __syncthreads();

    __shared__ float z[32];
    __shared__ float lg[NCLS];
    if (tid < 32) {
        float acc = lb1[tid];
#pragma unroll
        for (int k = 0; k < 64; k++) acc += p[k] * lw1[k * 32 + tid];
        z[tid] = fmaxf(acc, 0.0f);
    }
    __syncthreads();
    if (tid < NCLS) {
        float acc = lb2[tid];
#pragma unroll
        for (int k = 0; k < 32; k++) acc += z[k] * lw2[k * 10 + tid];
        lg[tid] = acc;
    }
    __syncthreads();
    if (tid == 0) {
        float m = lg[0];
#pragma unroll
        for (int c = 1; c < NCLS; c++) m = fmaxf(m, lg[c]);
        float se = 0.0f;
#pragma unroll
        for (int c = 0; c < NCLS; c++) se += expf(lg[c] - m);
        float l = m + logf(se);
#pragma unroll
        for (int c = 0; c < NCLS; c++) out[g * NCLS + c] = lg[c] - l;
    }
}

// ---------------- host ----------------
extern "C" void kernel_launch(void* const* d_in, const int* in_sizes, int n_in,
                              void* d_out, int out_size) {
    const float* x     = (const float*)d_in[0];
    const int*   ei    = (const int*)  d_in[1];
    const int*   batch = (const int*)  d_in[2];
    const float* W1  = (const float*)d_in[3];
    // b1 (d_in[4]) cancels inside BatchNorm
    const float* g1  = (const float*)d_in[5];
    const float* be1 = (const float*)d_in[6];
    const float* W2  = (const float*)d_in[7];
    // b2 (d_in[8]) cancels
    const float* g2  = (const float*)d_in[9];
    const float* be2 = (const float*)d_in[10];
    const float* lw1 = (const float*)d_in[11];
    const float* lb1 = (const float*)d_in[12];
    const float* lw2 = (const float*)d_in[13];
    const float* lb2 = (const float*)d_in[14];

    const int* src = ei;
    const int* dst = ei + N_EDGES;

    float *buf1, *buf2, *buf3, *dinv, *scale, *shift, *pool1;
    int *adj, *cnt, *cursor, *localex, *blksum, *done;
    int2* row2;
    double* psums;
    cudaGetSymbolAddress((void**)&buf1,   g_buf1);
    cudaGetSymbolAddress((void**)&buf2,   g_buf2);
    cudaGetSymbolAddress((void**)&buf3,   g_buf3);
    cudaGetSymbolAddress((void**)&adj,    g_adj);
    cudaGetSymbolAddress((void**)&cnt,    g_cnt);
    cudaGetSymbolAddress((void**)&row2,   g_row2);
    cudaGetSymbolAddress((void**)&cursor, g_cursor);
    cudaGetSymbolAddress((void**)&localex,g_localex);
    cudaGetSymbolAddress((void**)&blksum, g_blksum);
    cudaGetSymbolAddress((void**)&dinv,   g_dinv);
    cudaGetSymbolAddress((void**)&psums,  g_psums);
    cudaGetSymbolAddress((void**)&scale,  g_scale);
    cudaGetSymbolAddress((void**)&shift,  g_shift);
    cudaGetSymbolAddress((void**)&pool1,  g_pool1);
    cudaGetSymbolAddress((void**)&done,   g_done);

    const int TB = 256;
    const int init_blk = (ADJ_TOTAL + TB - 1) / TB;   // 6250
    const int n_blk    = (N_NODES + TB - 1) / TB;     // 782
    const int e4_blk   = (N_EDGES / 4 + TB - 1) / TB; // 977
    const int agg_blk  = N_NODES / 16;                // 12500
    const int gemm_blk = N_NODES / 64;                // 3125

    // ---- CSR build (gemm1 interleaved: independent, lands in profile slot) ----
    init_kernel     <<<init_blk, TB>>>(adj, cnt, psums, pool1, buf1, dinv, done);
    deg_count_kernel<<<e4_blk, TB>>>(dst, cnt);
    scanA_kernel    <<<SCAN_BLKS, 256>>>(cnt, localex, blksum);
    gemm64_kernel<false><<<gemm_blk, TB>>>(x, W1, nullptr, nullptr, nullptr, nullptr, buf1);
    scanC_kernel    <<<n_blk, 256>>>(localex, blksum, cnt, row2, cursor, dinv);
    scatter_kernel  <<<e4_blk, TB>>>(src, dst, cursor, adj);

    // ---- layer 1 (agg + BN stats + last-block finalize) ----
    agg_kernel<true><<<agg_blk, TB>>>(row2, adj, dinv, buf1, buf2, psums, done,
                                      g1, be1, scale, shift);

    // ---- layer 2 (BN1+relu fused on input; residual pooling fused) ----
    gemm64_kernel<true><<<gemm_blk, TB>>>(buf2, W2, scale, shift, batch, pool1, buf1);
    agg_kernel<false><<<agg_blk, TB>>>(row2, adj, dinv, buf1, buf3, psums + PSUM_STRIDE,
                                       nullptr, nullptr, nullptr, nullptr, nullptr);

    // ---- fused BN2-finalize + apply + pool + head ----
    poolhead_kernel<<<NGRAPH, 512>>>(buf3, pool1, psums + PSUM_STRIDE,
                                     g2, be2, batch, lw1, lb1, lw2, lb2, (float*)d_out);
}